// round 13
// baseline (speedup 1.0000x reference)
#include <cuda_runtime.h>
#include <cuda_bf16.h>

// Semi-CRF forward DP (HSCRF). B=16, L=128, T=11, K=7.
// R13: linear-domain publish. alpha rows are stored as S (linear, per-slot
// scale m): alpha = m + lg2(S). Every ex2/lg2 moves off the post-barrier
// critical path (factors depend only on scores + scale constants known a
// barrier ahead). Critical path: LDS S_e -> FFMA -> 4 shfl -> STS.
// 192 thr, x8 unroll (compile-time ring slots), software-pipelined k<=5
// partial, depth-3 prefetch, branch-free masking, in-kernel final reduction.

#define B_ 16
#define L_ 128
#define T_ 11
#define K_ 7
#define TT_ 121
#define NEGBIG  (-1e30f)
#define LOG2E_F 1.4426950408889634f
#define LN2_F   0.6931471805599453f
#define STEP_EL (129 * TT_)   /* elem offset per end-position step: 15609 */
#define KOFF_EL (128 * TT_)   /* elem offset per k: 15488 */

__device__ float g_partial[B_];
__device__ unsigned int g_tickets;   // one winner per launch (16 arrivals)

__device__ __forceinline__ float ex2f(float x) {
    float r; asm("ex2.approx.ftz.f32 %0, %1;" : "=f"(r) : "f"(x)); return r;
}
__device__ __forceinline__ float lg2f(float x) {
    float r; asm("lg2.approx.f32 %0, %1;" : "=f"(r) : "f"(x)); return r;
}

// One DP step at e = eb + U (computes S_{e+1}, scale Mcur).
// PFMODE 0: first block (compile-time j>=0 masks on prefetch)
//        1: steady state (no masks)
//        2: last block (skip prefetch when e+3 >= L_, compile-time)
#define DP_STEP(U, PFMODE)                                                     \
    do {                                                                       \
        /* ── post-barrier critical path (no MUFU) ── */                       \
        const float Se = a_lin[(U)][yp];         /* S_e[yp] */                 \
        float acc = fmaf(Se, f6, part);                                        \
        acc += __shfl_xor_sync(0xffffffffu, acc, 8, 16);                       \
        acc += __shfl_xor_sync(0xffffffffu, acc, 4, 16);                       \
        acc += __shfl_xor_sync(0xffffffffu, acc, 2, 16);                       \
        acc += __shfl_xor_sync(0xffffffffu, acc, 1, 16);                       \
        if (yp == 0) {                                                         \
            a_lin[((U) + 1) & 7][y] = acc;       /* publish S_{e+1} first */   \
            if (y == 0) r_ring[((U) + 1) & 7] = Mcur + lg2f(acc);              \
            if (y == T_ - 2 && (eb + (U) + 1) == len)                          \
                res = Mcur + lg2f(acc);                                        \
        }                                                                      \
        /* ── filler: scales, window shift, prefetch, next factors ── */       \
        const float Mn = r_ring[((U) + 7) & 7];  /* alpha_{e-1}[0] */          \
        _Pragma("unroll")                                                      \
        for (int k = 0; k < K_ - 1; k++) { av[k] = av[k + 1]; msc[k] = msc[k + 1]; } \
        av[K_ - 1]  = Se;     /* S_{e} */                                      \
        msc[K_ - 1] = Mprev;  /* scale of S_e = Mcur of step e-1 */            \
        if ((PFMODE) != 2 || (U) < 5) {                                        \
            _Pragma("unroll")                                                  \
            for (int k = 0; k < K_; k++) {                                     \
                bool ok = act;                                                 \
                if ((PFMODE) == 0) ok = ok && (k >= 3 - (U));                  \
                sb[((U) + 3) & 3][k] =                                         \
                    ok ? __ldg(pe + ((U) + 3) * STEP_EL + (k - 6) * KOFF_EL)   \
                       : NEGBIG;                                               \
            }                                                                  \
        }                                                                      \
        {   /* part for step e+1: k-th term uses S_{e-5+k} = av[k+1] */        \
            float p0 = 0.f, p1 = 0.f, p2 = 0.f;                                \
            _Pragma("unroll")                                                  \
            for (int k = 0; k < K_ - 1; k++) {                                 \
                float f = ex2f(fmaf(sb[((U) + 1) & 3][k], LOG2E_F,             \
                                    msc[k + 1] - Mn));                         \
                float t = av[k + 1] * f;                                       \
                if (k % 3 == 0) p0 += t; else if (k % 3 == 1) p1 += t;         \
                else p2 += t;                                                  \
            }                                                                  \
            part = (p0 + p1) + p2;                                             \
        }                                                                      \
        /* k=6 factor for step e+1: scale(S_{e+1}) = Mcur, new scale = Mn */   \
        f6 = ex2f(fmaf(sb[((U) + 1) & 3][6], LOG2E_F, Mcur - Mn));             \
        Mprev = Mcur; Mcur = Mn;                                               \
        __syncthreads();                                                       \
    } while (0)

__global__ void __launch_bounds__(192, 1)
dp_kernel(const float* __restrict__ scores, const int* __restrict__ mask,
          float* __restrict__ out) {
    const int tid = threadIdx.x;
    const int y   = tid >> 4;      // 0..11 (y==11 -> idle segment)
    const int yp  = tid & 15;      // 0..15 (yp>=11 -> padding lanes)
    const bool act = (y < T_) && (yp < T_);

    __shared__ float a_lin[8][16];   // S values (linear), [slot][label]
    __shared__ float r_ring[8];      // per-slot log2 alpha[slot][0] (scales)

    if (tid < 8) r_ring[tid] = 0.f;
    if (tid < 128) {
        int s = tid >> 4, c = tid & 15;
        // S_0: exp of alpha_0 under scale m=0 -> 1 at start label, else 0.
        a_lin[s][c] = (s == 0 && c == (T_ - 1)) ? 1.f : 0.f;
    }

    const int len = mask[blockIdx.x];  // in [64, 128]
    const float* base =
        scores + (size_t)blockIdx.x * (L_ * L_ * TT_) + (yp * T_ + y);

    // score ring sb[e&3][k]; prefill e = 0,1,2 (compile-time j>=0 masks)
    float sb[4][K_];
#pragma unroll
    for (int ee = 0; ee < 3; ee++)
#pragma unroll
        for (int k = 0; k < K_; k++)
            sb[ee][k] = (act && (ee - 6 + k) >= 0)
                            ? __ldg(base + ee * STEP_EL + (k - 6) * KOFF_EL)
                            : NEGBIG;

    // linear alpha window av[k] <-> S_{e-6+k}[yp]; msc[k] its scale
    float av[K_], msc[K_];
#pragma unroll
    for (int k = 0; k < K_; k++) { av[k] = 0.f; msc[k] = 0.f; }

    float part  = 0.f;   // step 0's k<=5 terms are all j<0 -> 0
    float Mcur  = 0.f;   // scale of S_1 (output of step 0)
    float Mprev = 0.f;   // scale of S_0
    float res   = 0.f;
    // k=6 factor for step 0: S_0 scale 0, Mcur 0
    float f6 = ex2f(sb[0][6] * LOG2E_F);
    __syncthreads();

    // ── peeled first block: eb = 0 ──
    {
        const int eb = 0;
        const float* pe = base;
        DP_STEP(0, 0); DP_STEP(1, 0); DP_STEP(2, 0); DP_STEP(3, 0);
        DP_STEP(4, 0); DP_STEP(5, 0); DP_STEP(6, 0); DP_STEP(7, 0);
    }

    // ── steady state: eb = 8 .. 112 ──
    {
        const float* pe = base;
#pragma unroll 1
        for (int eb = 8; eb <= 112; eb += 8) {
            pe += 8 * STEP_EL;
            DP_STEP(0, 1); DP_STEP(1, 1); DP_STEP(2, 1); DP_STEP(3, 1);
            DP_STEP(4, 1); DP_STEP(5, 1); DP_STEP(6, 1); DP_STEP(7, 1);
        }
    }

    // ── peeled last block: eb = 120 ──
    {
        const int eb = 120;
        const float* pe = base + 120 * STEP_EL;
        DP_STEP(0, 2); DP_STEP(1, 2); DP_STEP(2, 2); DP_STEP(3, 2);
        DP_STEP(4, 2); DP_STEP(5, 2); DP_STEP(6, 2); DP_STEP(7, 2);
    }

    if (yp == 0 && y == T_ - 2) g_partial[blockIdx.x] = res * LN2_F;
    __syncthreads();

    // last-finishing block sums the 16 partials (no separate reduce launch)
    if (tid == 0) {
        __threadfence();
        unsigned old = atomicAdd(&g_tickets, 1u);
        if ((old & (B_ - 1)) == (B_ - 1)) {
            __threadfence();
            float s = 0.f;
#pragma unroll
            for (int bb = 0; bb < B_; bb++)
                s += *((volatile float*)&g_partial[bb]);
            out[0] = s;
        }
    }
}

extern "C" void kernel_launch(void* const* d_in, const int* in_sizes, int n_in,
                              void* d_out, int out_size) {
    const float* scores = (const float*)d_in[0];
    const int*   mask   = (const int*)d_in[1];

    dp_kernel<<<B_, 192>>>(scores, mask, (float*)d_out);
}